// round 7
// baseline (speedup 1.0000x reference)
#include <cuda_runtime.h>
#include <cuda_fp16.h>
#include <cuda_pipeline.h>
#include <cstdint>

// Problem constants (fixed by the reference)
#define Bn    4
#define Cn    128
#define HWn   16384     // 128*128
#define Pn    4096
#define Vn    32
#define PT    8         // points per block (1 warp per point)
#define DEPTH 16        // cp.async ring depth (votes in flight per warp)

// Scratch for transposed x in fp16: [B][HW][C] half = 16.8 MB.
__device__ __align__(16) __half g_xt[(size_t)Bn * HWn * Cn];

// ---------------------------------------------------------------------------
// Kernel 1: transpose + downconvert x [B,C,HW] fp32 -> g_xt [B,HW,C] fp16.
// DRAM-roofline bound (~50MB); unchanged.
// ---------------------------------------------------------------------------
__global__ __launch_bounds__(256) void transpose_fp16_kernel(const float* __restrict__ x)
{
    __shared__ float tile[64][33];

    const int b   = blockIdx.z;
    const int hw0 = blockIdx.x * 32;
    const int c0  = blockIdx.y * 64;
    const int tx  = threadIdx.x;   // 0..31
    const int ty  = threadIdx.y;   // 0..7

    #pragma unroll
    for (int j = 0; j < 8; j++) {
        const int cl = ty + j * 8;
        tile[cl][tx] = x[((size_t)b * Cn + c0 + cl) * HWn + hw0 + tx];
    }
    __syncthreads();

    const int t = ty * 32 + tx;
    __half2* xt2 = reinterpret_cast<__half2*>(g_xt);
    #pragma unroll
    for (int j = 0; j < 4; j++) {
        const int idx  = j * 256 + t;
        const int hw_l = idx >> 5;
        const int c2   = idx & 31;
        const float f0 = tile[c2 * 2][hw_l];
        const float f1 = tile[c2 * 2 + 1][hw_l];
        xt2[(((size_t)b * HWn + hw0 + hw_l) * Cn + c0) / 2 + c2] = __floats2half2_rn(f0, f1);
    }
}

// ---------------------------------------------------------------------------
// Kernel 2: gather via cp.async smem ring. ONE WARP PER POINT.
// Lane l copies its own 8B channel slice of each vote row into the ring and
// later consumes exactly those bytes: per-lane wait_prior suffices, no syncs.
// 16 votes (4KB) in flight per warp, independent of register pressure.
// ---------------------------------------------------------------------------
__global__ __launch_bounds__(256) void gather_kernel(
    const int*   __restrict__ vote_index,   // [32768, 32]
    const float* __restrict__ vote_weight,  // [32768, 32]
    const int*   __restrict__ inds,         // [B, P] int32
    float*       __restrict__ out)          // [B, C, P]
{
    __shared__ uint32_t s_off[PT][Vn];   // hw * 256 (byte offset of row)
    __shared__ uint32_t s_w2[PT][Vn];    // half2(w, w) bit pattern
    __shared__ __align__(16) unsigned char s_ring[PT][DEPTH][256];
    __shared__ float s_out[PT][132];

    const int b    = blockIdx.y;
    const int p0   = blockIdx.x * PT;
    const int t    = threadIdx.x;
    const int warp = t >> 5;
    const int lane = t & 31;

    // Stage per-vote row offsets + weights (warp w stages point p0+w).
    {
        const int sph = inds[(size_t)b * Pn + p0 + warp];   // warp-uniform
        const int hw  = vote_index[(size_t)sph * Vn + lane];
        const float w = vote_weight[(size_t)sph * Vn + lane];
        const __half2 w2 = __float2half2_rn(w);
        s_off[warp][lane] = (unsigned)hw * 256u;
        s_w2[warp][lane]  = *reinterpret_cast<const unsigned*>(&w2);
    }
    __syncthreads();

    const char* xb = reinterpret_cast<const char*>(g_xt) + (size_t)b * HWn * 256;
    unsigned char* ring = &s_ring[warp][0][0];
    const int loff = lane * 8;           // this lane's channel slice in a row

    // Prologue: fill the ring with votes 0..15 (4 groups of 4).
    #pragma unroll
    for (int v = 0; v < DEPTH; v++) {
        __pipeline_memcpy_async(ring + v * 256 + loff,
                                xb + s_off[warp][v] + loff, 8);
        if ((v & 3) == 3) __pipeline_commit();
    }

    float2 accA = make_float2(0.f, 0.f);
    float2 accB = make_float2(0.f, 0.f);

    #pragma unroll
    for (int g = 0; g < Vn / 4; g++) {   // 8 groups of 4 votes
        __pipeline_wait_prior(3);        // group g's data is resident (per-lane)

        __half2 h0 = __float2half2_rn(0.f);
        __half2 h1 = __float2half2_rn(0.f);
        #pragma unroll
        for (int k = 0; k < 4; k++) {
            const int v    = g * 4 + k;
            const int slot = v & (DEPTH - 1);
            const uint2 d  = *reinterpret_cast<const uint2*>(ring + slot * 256 + loff);
            const unsigned wb = s_w2[warp][v];          // broadcast
            const __half2 w2  = *reinterpret_cast<const __half2*>(&wb);
            h0 = __hfma2(*reinterpret_cast<const __half2*>(&d.x), w2, h0);
            h1 = __hfma2(*reinterpret_cast<const __half2*>(&d.y), w2, h1);
        }
        const float2 f0 = __half22float2(h0);
        const float2 f1 = __half22float2(h1);
        accA.x += f0.x; accA.y += f0.y;
        accB.x += f1.x; accB.y += f1.y;

        // Refill: votes 16+4g .. 19+4g (reuses just-consumed slots; the async
        // write lands hundreds of cycles after this lane's LDS was serviced).
        // Past the end, commit EMPTY groups so wait_prior(3) stays uniform.
        if (g < 4) {
            #pragma unroll
            for (int k = 0; k < 4; k++) {
                const int v    = DEPTH + g * 4 + k;
                const int slot = v & (DEPTH - 1);
                __pipeline_memcpy_async(ring + slot * 256 + loff,
                                        xb + s_off[warp][v] + loff, 8);
            }
            __pipeline_commit();
        } else {
            __pipeline_commit();         // empty group keeps the count moving
        }
    }

    *reinterpret_cast<float4*>(&s_out[warp][lane * 4]) =
        make_float4(accA.x, accA.y, accB.x, accB.y);
    __syncthreads();

    // Write out [C][PT] tile: 8 consecutive p per c row.
    #pragma unroll
    for (int i = t; i < Cn * PT; i += 256) {
        const int c  = i >> 3;   // i / PT
        const int pl = i & 7;    // i % PT
        out[((size_t)b * Cn + c) * Pn + p0 + pl] = s_out[pl][c];
    }
}

// ---------------------------------------------------------------------------
// Launch
// ---------------------------------------------------------------------------
extern "C" void kernel_launch(void* const* d_in, const int* in_sizes, int n_in,
                              void* d_out, int out_size)
{
    const float* x           = (const float*)d_in[0];   // [4,128,128,128]
    const int*   vote_index  = (const int*)d_in[1];     // [32768,32]
    const float* vote_weight = (const float*)d_in[2];   // [32768,32]
    const int*   inds        = (const int*)d_in[3];     // [4,4096] int32
    float*       out         = (float*)d_out;           // [4,128,4096]

    {
        dim3 grid(HWn / 32, Cn / 64, Bn);   // (512, 2, 4)
        dim3 block(32, 8);
        transpose_fp16_kernel<<<grid, block>>>(x);
    }
    {
        dim3 grid(Pn / PT, Bn);             // (512, 4) = 2048 blocks
        gather_kernel<<<grid, 256>>>(vote_index, vote_weight, inds, out);
    }
}

// round 8
// speedup vs baseline: 1.3798x; 1.3798x over previous
#include <cuda_runtime.h>
#include <cuda_fp16.h>
#include <cstdint>

// Problem constants (fixed by the reference)
#define Bn   4
#define Cn   128
#define HWn  16384      // 128*128
#define Pn   4096
#define Vn   32
#define PT   8          // points per block (1 warp per point)

// Scratch for transposed x in fp16: [B][HW][C] half = 16.8 MB.
__device__ __align__(16) __half g_xt[(size_t)Bn * HWn * Cn];

// ---------------------------------------------------------------------------
// Kernel 1: transpose + downconvert x [B,C,HW] fp32 -> g_xt [B,HW,C] fp16.
// ---------------------------------------------------------------------------
__global__ __launch_bounds__(256) void transpose_fp16_kernel(const float* __restrict__ x)
{
    __shared__ float tile[64][33];

    const int b   = blockIdx.z;
    const int hw0 = blockIdx.x * 32;
    const int c0  = blockIdx.y * 64;
    const int tx  = threadIdx.x;   // 0..31
    const int ty  = threadIdx.y;   // 0..7

    #pragma unroll
    for (int j = 0; j < 8; j++) {
        const int cl = ty + j * 8;
        tile[cl][tx] = x[((size_t)b * Cn + c0 + cl) * HWn + hw0 + tx];
    }
    __syncthreads();

    const int t = ty * 32 + tx;
    __half2* xt2 = reinterpret_cast<__half2*>(g_xt);
    #pragma unroll
    for (int j = 0; j < 4; j++) {
        const int idx  = j * 256 + t;
        const int hw_l = idx >> 5;
        const int c2   = idx & 31;
        const float f0 = tile[c2 * 2][hw_l];
        const float f1 = tile[c2 * 2 + 1][hw_l];
        xt2[(((size_t)b * HWn + hw0 + hw_l) * Cn + c0) / 2 + c2] = __floats2half2_rn(f0, f1);
    }
}

// ---------------------------------------------------------------------------
// Kernel 2: gather + vote accumulate. ONE WARP PER POINT.
// Explicit 16-deep register pipeline: prologue issues 16 vote gathers (4KB
// in flight per warp); each slot is refilled right after consumption, so the
// refill has 15 slots (~200+ cyc of other work) before its own consumption.
// __launch_bounds__(256,5): 51-reg budget so the pipeline actually fits
// (the old (256,6)=42-reg cap is what prevented cross-group overlap).
// ---------------------------------------------------------------------------
__global__ __launch_bounds__(256, 5) void gather_kernel(
    const int*   __restrict__ vote_index,   // [32768, 32]
    const float* __restrict__ vote_weight,  // [32768, 32]
    const int*   __restrict__ inds,         // [B, P] int32
    float*       __restrict__ out)          // [B, C, P]
{
    __shared__ uint2 s_iw[PT][Vn];   // {hw * (Cn/4) offset, half2(w,w) bits}
    __shared__ float s_out[PT][132];

    const int b    = blockIdx.y;
    const int p0   = blockIdx.x * PT;
    const int t    = threadIdx.x;
    const int warp = t >> 5;
    const int lane = t & 31;

    // Stage fused (row offset in uint2 units, weight half2) per vote.
    {
        const int sph = inds[(size_t)b * Pn + p0 + warp];   // warp-uniform
        const int hw  = vote_index[(size_t)sph * Vn + lane];
        const float w = vote_weight[(size_t)sph * Vn + lane];
        const __half2 w2 = __float2half2_rn(w);
        s_iw[warp][lane] = make_uint2((unsigned)hw * (Cn / 4),
                                      *reinterpret_cast<const unsigned*>(&w2));
    }
    __syncthreads();

    // Row = 128 halves = 32 uint2; lane l owns uint2 l (channels 4l..4l+3).
    const uint2* xt = reinterpret_cast<const uint2*>(g_xt) + (size_t)b * HWn * (Cn / 4);

    // Prologue: 16 independent gathers in flight.
    uint2 r[16];
    #pragma unroll
    for (int v = 0; v < 16; v++) {
        r[v] = __ldg(&xt[s_iw[warp][v].x + lane]);
    }

    float2 accA = make_float2(0.f, 0.f);
    float2 accB = make_float2(0.f, 0.f);

    #pragma unroll
    for (int g = 0; g < Vn / 4; g++) {       // 8 groups of 4 votes
        __half2 h0 = __float2half2_rn(0.f);
        __half2 h1 = __float2half2_rn(0.f);
        #pragma unroll
        for (int k = 0; k < 4; k++) {
            const int v    = g * 4 + k;
            const int slot = v & 15;
            const unsigned wb = s_iw[warp][v].y;              // LDS broadcast
            const __half2 w2  = *reinterpret_cast<const __half2*>(&wb);
            h0 = __hfma2(*reinterpret_cast<const __half2*>(&r[slot].x), w2, h0);
            h1 = __hfma2(*reinterpret_cast<const __half2*>(&r[slot].y), w2, h1);
            if (g < 4) {                      // refill slot with vote v+16
                r[slot] = __ldg(&xt[s_iw[warp][v + 16].x + lane]);
            }
        }
        const float2 f0 = __half22float2(h0);
        const float2 f1 = __half22float2(h1);
        accA.x += f0.x; accA.y += f0.y;
        accB.x += f1.x; accB.y += f1.y;
    }

    *reinterpret_cast<float4*>(&s_out[warp][lane * 4]) =
        make_float4(accA.x, accA.y, accB.x, accB.y);
    __syncthreads();

    // Write out [C][PT] tile: 8 consecutive p per c row.
    #pragma unroll
    for (int i = t; i < Cn * PT; i += 256) {
        const int c  = i >> 3;   // i / PT
        const int pl = i & 7;    // i % PT
        out[((size_t)b * Cn + c) * Pn + p0 + pl] = s_out[pl][c];
    }
}

// ---------------------------------------------------------------------------
// Launch
// ---------------------------------------------------------------------------
extern "C" void kernel_launch(void* const* d_in, const int* in_sizes, int n_in,
                              void* d_out, int out_size)
{
    const float* x           = (const float*)d_in[0];   // [4,128,128,128]
    const int*   vote_index  = (const int*)d_in[1];     // [32768,32]
    const float* vote_weight = (const float*)d_in[2];   // [32768,32]
    const int*   inds        = (const int*)d_in[3];     // [4,4096] int32
    float*       out         = (float*)d_out;           // [4,128,4096]

    {
        dim3 grid(HWn / 32, Cn / 64, Bn);   // (512, 2, 4)
        dim3 block(32, 8);
        transpose_fp16_kernel<<<grid, block>>>(x);
    }
    {
        dim3 grid(Pn / PT, Bn);             // (512, 4) = 2048 blocks
        gather_kernel<<<grid, 256>>>(vote_index, vote_weight, inds, out);
    }
}

// round 9
// speedup vs baseline: 1.4431x; 1.0458x over previous
#include <cuda_runtime.h>
#include <cuda_fp16.h>
#include <cstdint>

// Problem constants (fixed by the reference)
#define Bn   4
#define Cn   128
#define HWn  16384      // 128*128
#define Pn   4096
#define Vn   32
#define PT   8          // points per block (1 warp per point)

// Scratch for transposed x in fp16: [B][HW][C] half = 16.8 MB.
__device__ __align__(16) __half g_xt[(size_t)Bn * HWn * Cn];

// ---------------------------------------------------------------------------
// Kernel 1: transpose + downconvert x [B,C,HW] fp32 -> g_xt [B,HW,C] fp16.
// DRAM-roofline bound (~50MB @ ~7.8TB/s); unchanged.
// ---------------------------------------------------------------------------
__global__ __launch_bounds__(256) void transpose_fp16_kernel(const float* __restrict__ x)
{
    __shared__ float tile[64][33];

    const int b   = blockIdx.z;
    const int hw0 = blockIdx.x * 32;
    const int c0  = blockIdx.y * 64;
    const int tx  = threadIdx.x;   // 0..31
    const int ty  = threadIdx.y;   // 0..7

    #pragma unroll
    for (int j = 0; j < 8; j++) {
        const int cl = ty + j * 8;
        tile[cl][tx] = x[((size_t)b * Cn + c0 + cl) * HWn + hw0 + tx];
    }
    __syncthreads();

    const int t = ty * 32 + tx;
    __half2* xt2 = reinterpret_cast<__half2*>(g_xt);
    #pragma unroll
    for (int j = 0; j < 4; j++) {
        const int idx  = j * 256 + t;
        const int hw_l = idx >> 5;
        const int c2   = idx & 31;
        const float f0 = tile[c2 * 2][hw_l];
        const float f1 = tile[c2 * 2 + 1][hw_l];
        xt2[(((size_t)b * HWn + hw0 + hw_l) * Cn + c0) / 2 + c2] = __floats2half2_rn(f0, f1);
    }
}

// ---------------------------------------------------------------------------
// Kernel 2: gather + vote accumulate. ONE WARP PER POINT.
// Measured law across r2..r8: T_gather ~= 10.5us / occupancy (pure warp-
// concurrency limit). So: __launch_bounds__(256, 8) -> 32-reg budget ->
// 8 blocks/SM -> 64 warps/SM (100% theoretical occupancy).
// Body is the reg-lean r5 form: group of 4 LDG.64 + HFMA2, fp32 flush/group.
// ---------------------------------------------------------------------------
__global__ __launch_bounds__(256, 8) void gather_kernel(
    const int*   __restrict__ vote_index,   // [32768, 32]
    const float* __restrict__ vote_weight,  // [32768, 32]
    const int*   __restrict__ inds,         // [B, P] int32
    float*       __restrict__ out)          // [B, C, P]
{
    __shared__ uint2 s_iw[PT][Vn];   // {hw * (Cn/4) offset, half2(w,w) bits}
    __shared__ float s_out[PT][132];

    const int b    = blockIdx.y;
    const int p0   = blockIdx.x * PT;
    const int t    = threadIdx.x;
    const int warp = t >> 5;
    const int lane = t & 31;

    // Stage fused (row offset in uint2 units, weight half2) per vote.
    {
        const int sph = inds[(size_t)b * Pn + p0 + warp];   // warp-uniform
        const int hw  = vote_index[(size_t)sph * Vn + lane];
        const float w = vote_weight[(size_t)sph * Vn + lane];
        const __half2 w2 = __float2half2_rn(w);
        s_iw[warp][lane] = make_uint2((unsigned)hw * (Cn / 4),
                                      *reinterpret_cast<const unsigned*>(&w2));
    }
    __syncthreads();

    // Row = 128 halves = 32 uint2; lane l owns uint2 l (channels 4l..4l+3).
    const uint2* xt = reinterpret_cast<const uint2*>(g_xt) + (size_t)b * HWn * (Cn / 4);

    float2 accA = make_float2(0.f, 0.f);
    float2 accB = make_float2(0.f, 0.f);

    #pragma unroll
    for (int g = 0; g < Vn / 4; g++) {           // 8 groups of 4 votes
        // 4 independent gathers, then the HFMA2 chain.
        uint2 iw0 = s_iw[warp][g * 4 + 0];
        uint2 iw1 = s_iw[warp][g * 4 + 1];
        uint2 iw2 = s_iw[warp][g * 4 + 2];
        uint2 iw3 = s_iw[warp][g * 4 + 3];
        const uint2 r0 = __ldg(&xt[iw0.x + lane]);
        const uint2 r1 = __ldg(&xt[iw1.x + lane]);
        const uint2 r2 = __ldg(&xt[iw2.x + lane]);
        const uint2 r3 = __ldg(&xt[iw3.x + lane]);

        __half2 h0 = __float2half2_rn(0.f);
        __half2 h1 = __float2half2_rn(0.f);
        h0 = __hfma2(*reinterpret_cast<const __half2*>(&r0.x),
                     *reinterpret_cast<const __half2*>(&iw0.y), h0);
        h1 = __hfma2(*reinterpret_cast<const __half2*>(&r0.y),
                     *reinterpret_cast<const __half2*>(&iw0.y), h1);
        h0 = __hfma2(*reinterpret_cast<const __half2*>(&r1.x),
                     *reinterpret_cast<const __half2*>(&iw1.y), h0);
        h1 = __hfma2(*reinterpret_cast<const __half2*>(&r1.y),
                     *reinterpret_cast<const __half2*>(&iw1.y), h1);
        h0 = __hfma2(*reinterpret_cast<const __half2*>(&r2.x),
                     *reinterpret_cast<const __half2*>(&iw2.y), h0);
        h1 = __hfma2(*reinterpret_cast<const __half2*>(&r2.y),
                     *reinterpret_cast<const __half2*>(&iw2.y), h1);
        h0 = __hfma2(*reinterpret_cast<const __half2*>(&r3.x),
                     *reinterpret_cast<const __half2*>(&iw3.y), h0);
        h1 = __hfma2(*reinterpret_cast<const __half2*>(&r3.y),
                     *reinterpret_cast<const __half2*>(&iw3.y), h1);

        const float2 f0 = __half22float2(h0);
        const float2 f1 = __half22float2(h1);
        accA.x += f0.x; accA.y += f0.y;
        accB.x += f1.x; accB.y += f1.y;
    }

    *reinterpret_cast<float4*>(&s_out[warp][lane * 4]) =
        make_float4(accA.x, accA.y, accB.x, accB.y);
    __syncthreads();

    // Write out [C][PT] tile: 8 consecutive p per c row.
    #pragma unroll
    for (int i = t; i < Cn * PT; i += 256) {
        const int c  = i >> 3;   // i / PT
        const int pl = i & 7;    // i % PT
        out[((size_t)b * Cn + c) * Pn + p0 + pl] = s_out[pl][c];
    }
}

// ---------------------------------------------------------------------------
// Launch
// ---------------------------------------------------------------------------
extern "C" void kernel_launch(void* const* d_in, const int* in_sizes, int n_in,
                              void* d_out, int out_size)
{
    const float* x           = (const float*)d_in[0];   // [4,128,128,128]
    const int*   vote_index  = (const int*)d_in[1];     // [32768,32]
    const float* vote_weight = (const float*)d_in[2];   // [32768,32]
    const int*   inds        = (const int*)d_in[3];     // [4,4096] int32
    float*       out         = (float*)d_out;           // [4,128,4096]

    {
        dim3 grid(HWn / 32, Cn / 64, Bn);   // (512, 2, 4)
        dim3 block(32, 8);
        transpose_fp16_kernel<<<grid, block>>>(x);
    }
    {
        dim3 grid(Pn / PT, Bn);             // (512, 4) = 2048 blocks
        gather_kernel<<<grid, 256>>>(vote_index, vote_weight, inds, out);
    }
}